// round 6
// baseline (speedup 1.0000x reference)
#include <cuda_runtime.h>
#include <cuda_bf16.h>
#include <cstdint>

#define NB 65536
#define SS 5
#define KK 4
#define DD 12
#define HH 48
#define NCB 32        // batch rows per LSTM CTA
#define TPB_L 384     // 48 d  x  8 n-quads

typedef unsigned long long ull;

__device__ float g_xbuf[SS * HH * NB];        // [s][feat][n]
__device__ float g_hst[2][(size_t)HH * NB];   // final hidden per dir, [d][n]

// ---------------- helpers ----------------
__device__ __forceinline__ float sigf(float x) {
    return __fdividef(1.0f, 1.0f + __expf(-x));
}
__device__ __forceinline__ float tanhf_(float x) {
    return 1.0f - __fdividef(2.0f, __expf(2.0f * x) + 1.0f);
}
__device__ __forceinline__ ull pack2(float lo, float hi) {
    ull r; asm("mov.b64 %0, {%1, %2};" : "=l"(r) : "f"(lo), "f"(hi)); return r;
}
__device__ __forceinline__ void unpack2(ull v, float& lo, float& hi) {
    asm("mov.b64 {%0, %1}, %2;" : "=f"(lo), "=f"(hi) : "l"(v));
}
__device__ __forceinline__ float red2(ull v) {
    float lo, hi; unpack2(v, lo, hi); return lo + hi;
}
__device__ __forceinline__ void fma2(ull& acc, ull a, ull b) {
    asm("fma.rn.f32x2 %0, %1, %2, %0;" : "+l"(acc) : "l"(a), "l"(b));
}

// ===========================================================================
// Kernel A: GNN message passing (identical to the 711us-passing version)
// ===========================================================================
__global__ __launch_bounds__(128) void gnn_kernel(
    const float* __restrict__ nf, const float* __restrict__ pos,
    const float* __restrict__ att,
    const float* __restrict__ msgw, const float* __restrict__ msgb,
    const float* __restrict__ gwi, const float* __restrict__ gwh,
    const float* __restrict__ gbi, const float* __restrict__ gbh)
{
    __shared__ float      s_mw[144];
    __shared__ float      s_mb[12];
    __shared__ ulonglong2 sRZ[144];
    __shared__ ull        sN [144];
    __shared__ ull        sBR[12], sBZ[12], sBN[12];

    int tid = threadIdx.x;
    for (int i = tid; i < 144; i += 128) {
        s_mw[i] = msgw[i];
        int d = i / 12, e = i - d * 12;
        ulonglong2 t;
        t.x = pack2(gwi[d * 12 + e],        gwh[d * 12 + e]);
        t.y = pack2(gwi[(12 + d) * 12 + e], gwh[(12 + d) * 12 + e]);
        sRZ[i] = t;
        sN[i]  = pack2(gwi[(24 + d) * 12 + e], gwh[(24 + d) * 12 + e]);
    }
    if (tid < 12) {
        s_mb[tid] = msgb[tid];
        sBR[tid] = pack2(gbi[tid] + gbh[tid], 0.f);
        sBZ[tid] = pack2(gbi[12 + tid] + gbh[12 + tid], 0.f);
        sBN[tid] = pack2(gbi[24 + tid], gbh[24 + tid]);
    }
    __syncthreads();

    int n = blockIdx.x * 128 + tid;
    int s = blockIdx.y;
    int base = n * SS + s;

    float h[KK][DD];
    {
        float t[24];
        const float4* p4 = reinterpret_cast<const float4*>(nf + (size_t)base * 24);
        #pragma unroll
        for (int i = 0; i < 6; i++) {
            float4 v = p4[i];
            t[4*i] = v.x; t[4*i+1] = v.y; t[4*i+2] = v.z; t[4*i+3] = v.w;
        }
        #pragma unroll
        for (int i = 0; i < 24; i++) h[i / 6][i % 6] = t[i];
        const float4* q4 = reinterpret_cast<const float4*>(pos + (size_t)base * 24);
        #pragma unroll
        for (int i = 0; i < 6; i++) {
            float4 v = q4[i];
            t[4*i] = v.x; t[4*i+1] = v.y; t[4*i+2] = v.z; t[4*i+3] = v.w;
        }
        #pragma unroll
        for (int i = 0; i < 24; i++) h[i / 6][6 + i % 6] = t[i];
    }
    float a[KK][KK];
    {
        const float4* a4 = reinterpret_cast<const float4*>(att + (size_t)base * 16);
        #pragma unroll
        for (int k = 0; k < 4; k++) {
            float4 v = a4[k];
            a[k][0] = v.x; a[k][1] = v.y; a[k][2] = v.z; a[k][3] = v.w;
        }
    }

    #pragma unroll 1
    for (int pass = 0; pass < 2; pass++) {
        float hl[48];
        #pragma unroll
        for (int k = 0; k < 4; k++)
            #pragma unroll
            for (int d = 0; d < 12; d++) hl[k * 12 + d] = h[k][d];

        float mv[KK][DD];
        #pragma unroll
        for (int d = 0; d < 12; d++) {
            float ma[4];
            #pragma unroll
            for (int w = 0; w < 4; w++) {
                float acc = s_mb[d];
                #pragma unroll
                for (int e = 0; e < 12; e++) acc += s_mw[d * 12 + e] * h[w][e];
                ma[w] = acc;
            }
            #pragma unroll
            for (int k = 0; k < 4; k++)
                mv[k][d] = a[k][0]*ma[0] + a[k][1]*ma[1] + a[k][2]*ma[2] + a[k][3]*ma[3];
        }

        #pragma unroll
        for (int k = 0; k < 4; k++) {
            ull gk[12];
            #pragma unroll
            for (int e = 0; e < 12; e++) gk[e] = pack2(mv[k][e], h[k][e]);
            float tmpl[12];
            #pragma unroll 1
            for (int d = 0; d < 12; d++) {
                ull aR = sBR[d], aZ = sBZ[d], aN = sBN[d];
                const ulonglong2* wrz = sRZ + d * 12;
                const ull*        wn  = sN  + d * 12;
                #pragma unroll
                for (int e = 0; e < 12; e++) {
                    ulonglong2 w = wrz[e];
                    fma2(aR, w.x, gk[e]);
                    fma2(aZ, w.y, gk[e]);
                    fma2(aN, wn[e], gk[e]);
                }
                float r = sigf(red2(aR));
                float z = sigf(red2(aZ));
                float nlo, nhi; unpack2(aN, nlo, nhi);
                float nn = tanhf_(nlo + r * nhi);
                tmpl[d] = (1.0f - z) * nn + z * hl[k * 12 + d];
            }
            #pragma unroll
            for (int d = 0; d < 12; d++) h[k][d] = tmpl[d];
        }
    }

    #pragma unroll
    for (int k = 0; k < 4; k++)
        #pragma unroll
        for (int d = 0; d < 12; d++)
            g_xbuf[(size_t)(s * HH + d * 4 + k) * NB + n] = h[k][d];
}

// ===========================================================================
// Kernel B: register-tiled bidirectional LSTM.
// Thread (d, q): output dim d (gates I,F,G,O) for 4 batch rows n = nb+q*4..+3.
// Accumulators are k-pair partial sums (f32x2), act buffer [kp][n] in smem.
// ===========================================================================
#define O_W   0                     /* ull[48*48*4] = 73728 B */
#define O_ACT 73728                 /* ull[48*32]  = 12288 B */
#define O_B   (73728 + 12288)       /* float[192] */
#define SMEM_L (O_B + 768 + 16)

__global__ __launch_bounds__(TPB_L, 2) void lstm_rt_kernel(
    const float* __restrict__ wihF, const float* __restrict__ whhF,
    const float* __restrict__ bihF, const float* __restrict__ bhhF,
    const float* __restrict__ wihB, const float* __restrict__ whhB,
    const float* __restrict__ bihB, const float* __restrict__ bhhB)
{
    extern __shared__ char smc[];
    ull*   sW   = (ull*)(smc + O_W);     // [d][kp][g] = (w[2kp], w[2kp+1])
    ull*   sAct = (ull*)(smc + O_ACT);   // [kp][n]: kp<24 x-pairs, >=24 h-pairs
    float* sB   = (float*)(smc + O_B);   // [d*4+g]

    int tid = threadIdx.x;
    int d = tid >> 3;       // 0..47
    int q = tid & 7;        // 0..7  -> n = nb + q*4 .. +3
    int nb = blockIdx.x * NCB;

    #pragma unroll 1
    for (int dir = 0; dir < 2; dir++) {
        const float* wih = dir ? wihB : wihF;
        const float* whh = dir ? whhB : whhF;
        const float* bih = dir ? bihB : bihF;
        const float* bhh = dir ? bhhB : bhhF;

        __syncthreads();   // everyone done with previous dir's sW
        // stage weights as k-pair ulls: sW[(d*48+kp)*4+g]
        for (int i = tid; i < 9216; i += TPB_L) {
            int dd = i / 192;
            int r  = i - dd * 192;
            int kp = r >> 2, g = r & 3;
            int k0 = 2 * kp;
            float w0, w1;
            if (k0 < 48) {
                w0 = wih[(g * 48 + dd) * 48 + k0];
                w1 = wih[(g * 48 + dd) * 48 + k0 + 1];
            } else {
                w0 = whh[(g * 48 + dd) * 48 + (k0 - 48)];
                w1 = whh[(g * 48 + dd) * 48 + (k0 - 47)];
            }
            sW[i] = pack2(w0, w1);
        }
        for (int i = tid; i < 192; i += TPB_L) {
            int dd = i >> 2, g = i & 3;
            sB[i] = bih[g * 48 + dd] + bhh[g * 48 + dd];
        }
        // zero h half of act buffer
        for (int i = tid; i < 24 * 32; i += TPB_L)
            sAct[(24 + (i >> 5)) * 32 + (i & 31)] = 0ull;
        __syncthreads();

        float b0 = sB[d * 4 + 0], b1 = sB[d * 4 + 1];
        float b2 = sB[d * 4 + 2], b3 = sB[d * 4 + 3];
        float c[4] = {0.f, 0.f, 0.f, 0.f};

        #pragma unroll 1
        for (int st = 0; st < SS; st++) {
            int s = dir ? (SS - 1 - st) : st;
            // load x pairs into act[0..23][*]
            #pragma unroll
            for (int rr = 0; rr < 2; rr++) {
                int i = tid + rr * TPB_L;
                int kp = i >> 5, n = i & 31;
                sAct[kp * 32 + n] =
                    pack2(g_xbuf[(size_t)(s * HH + 2 * kp) * NB + nb + n],
                          g_xbuf[(size_t)(s * HH + 2 * kp + 1) * NB + nb + n]);
            }
            __syncthreads();

            ull acc[4][4];
            #pragma unroll
            for (int g = 0; g < 4; g++)
                #pragma unroll
                for (int u = 0; u < 4; u++) acc[g][u] = 0ull;

            const ulonglong2* wrow = (const ulonglong2*)(sW + d * 192);
            #pragma unroll 8
            for (int kp = 0; kp < 48; kp++) {
                ulonglong2 wA = wrow[kp * 2];        // (wI, wF)
                ulonglong2 wB = wrow[kp * 2 + 1];    // (wG, wO)
                const ulonglong2* ap = (const ulonglong2*)(sAct + kp * 32 + q * 4);
                ulonglong2 aA = ap[0];
                ulonglong2 aB = ap[1];
                fma2(acc[0][0], wA.x, aA.x); fma2(acc[1][0], wA.y, aA.x);
                fma2(acc[2][0], wB.x, aA.x); fma2(acc[3][0], wB.y, aA.x);
                fma2(acc[0][1], wA.x, aA.y); fma2(acc[1][1], wA.y, aA.y);
                fma2(acc[2][1], wB.x, aA.y); fma2(acc[3][1], wB.y, aA.y);
                fma2(acc[0][2], wA.x, aB.x); fma2(acc[1][2], wA.y, aB.x);
                fma2(acc[2][2], wB.x, aB.x); fma2(acc[3][2], wB.y, aB.x);
                fma2(acc[0][3], wA.x, aB.y); fma2(acc[1][3], wA.y, aB.y);
                fma2(acc[2][3], wB.x, aB.y); fma2(acc[3][3], wB.y, aB.y);
            }
            __syncthreads();   // all reads of sAct done

            float hv[4];
            #pragma unroll
            for (int u = 0; u < 4; u++) {
                float pI = red2(acc[0][u]) + b0;
                float pF = red2(acc[1][u]) + b1;
                float pG = red2(acc[2][u]) + b2;
                float pO = red2(acc[3][u]) + b3;
                float ig = sigf(pI), fg = sigf(pF);
                float gg = tanhf_(pG), og = sigf(pO);
                float cn = fg * c[u] + ig * gg;
                c[u] = cn;
                hv[u] = og * tanhf_(cn);
            }

            if (st < SS - 1) {
                float* sAf = (float*)sAct;
                int kp_h = 24 + (d >> 1), par = d & 1;
                #pragma unroll
                for (int u = 0; u < 4; u++)
                    sAf[(kp_h * 32 + q * 4 + u) * 2 + par] = hv[u];
            } else {
                float4 o4 = make_float4(hv[0], hv[1], hv[2], hv[3]);
                *(float4*)&g_hst[dir][(size_t)d * NB + nb + q * 4] = o4;
            }
        } // st
    } // dir
}

// ===========================================================================
// Kernel C: MLP head, one thread per n (f32x2 pairs), smem weights
// ===========================================================================
__global__ __launch_bounds__(256) void mlp_kernel(
    const float* __restrict__ e1w, const float* __restrict__ e1b,
    const float* __restrict__ e2w, const float* __restrict__ e2b,
    const float* __restrict__ e3w, const float* __restrict__ e3b,
    float* __restrict__ out)
{
    __shared__ ull   m1p[2304];
    __shared__ float m1b[48], m2[1728], m2b[36], m3[216], m3b[6];

    int tid = threadIdx.x;
    for (int i = tid; i < 2304; i += 256) {
        int ii = i / 48, j = i - ii * 48;
        m1p[i] = pack2(e1w[ii * 96 + j], e1w[ii * 96 + 48 + j]);
    }
    for (int i = tid; i < 1728; i += 256) m2[i] = e2w[i];
    for (int i = tid; i < 216;  i += 256) m3[i] = e3w[i];
    if (tid < 48) m1b[tid] = e1b[tid];
    if (tid < 36) m2b[tid] = e2b[tid];
    if (tid < 6)  m3b[tid] = e3b[tid];
    __syncthreads();

    int n = blockIdx.x * 256 + tid;

    ull av[48];
    #pragma unroll
    for (int j = 0; j < 48; j++)
        av[j] = pack2(g_hst[0][(size_t)j * NB + n], g_hst[1][(size_t)j * NB + n]);

    float x1l[48];
    #pragma unroll 1
    for (int i = 0; i < 48; i++) {
        ull acc = pack2(m1b[i], 0.f);
        const ull* w = m1p + i * 48;
        #pragma unroll
        for (int j = 0; j < 48; j++) fma2(acc, w[j], av[j]);
        x1l[i] = fmaxf(red2(acc), 0.f);
    }
    #pragma unroll
    for (int j = 0; j < 24; j++) av[j] = pack2(x1l[2*j], x1l[2*j+1]);
    const ull* m2p = (const ull*)m2;
    float x2l[36];
    #pragma unroll 1
    for (int i = 0; i < 36; i++) {
        ull acc = pack2(m2b[i], 0.f);
        const ull* w = m2p + i * 24;
        #pragma unroll
        for (int j = 0; j < 24; j++) fma2(acc, w[j], av[j]);
        x2l[i] = fmaxf(red2(acc), 0.f);
    }
    #pragma unroll
    for (int j = 0; j < 18; j++) av[j] = pack2(x2l[2*j], x2l[2*j+1]);
    const ull* m3p = (const ull*)m3;
    #pragma unroll
    for (int cc = 0; cc < 6; cc++) {
        ull acc = pack2(m3b[cc], 0.f);
        const ull* w = m3p + cc * 18;
        #pragma unroll
        for (int j = 0; j < 18; j++) fma2(acc, w[j], av[j]);
        out[(size_t)n * 6 + cc] = red2(acc);
    }
}

// ===========================================================================
extern "C" void kernel_launch(void* const* d_in, const int* in_sizes, int n_in,
                              void* d_out, int out_size)
{
    const float* nf   = (const float*)d_in[0];
    const float* pos  = (const float*)d_in[1];
    const float* att  = (const float*)d_in[2];
    const float* msgw = (const float*)d_in[3];
    const float* msgb = (const float*)d_in[4];
    const float* gwi  = (const float*)d_in[5];
    const float* gwh  = (const float*)d_in[6];
    const float* gbi  = (const float*)d_in[7];
    const float* gbh  = (const float*)d_in[8];
    const float* wihF = (const float*)d_in[9];
    const float* whhF = (const float*)d_in[10];
    const float* bihF = (const float*)d_in[11];
    const float* bhhF = (const float*)d_in[12];
    const float* wihB = (const float*)d_in[13];
    const float* whhB = (const float*)d_in[14];
    const float* bihB = (const float*)d_in[15];
    const float* bhhB = (const float*)d_in[16];
    const float* e1w  = (const float*)d_in[17];
    const float* e1b  = (const float*)d_in[18];
    const float* e2w  = (const float*)d_in[19];
    const float* e2b  = (const float*)d_in[20];
    const float* e3w  = (const float*)d_in[21];
    const float* e3b  = (const float*)d_in[22];
    float* out = (float*)d_out;

    cudaFuncSetAttribute(lstm_rt_kernel,
                         cudaFuncAttributeMaxDynamicSharedMemorySize, SMEM_L);

    dim3 gA(NB / 128, SS);
    gnn_kernel<<<gA, 128>>>(nf, pos, att, msgw, msgb, gwi, gwh, gbi, gbh);
    lstm_rt_kernel<<<NB / NCB, TPB_L, SMEM_L>>>(
        wihF, whhF, bihF, bhhF, wihB, whhB, bihB, bhhB);
    mlp_kernel<<<NB / 256, 256>>>(e1w, e1b, e2w, e2b, e3w, e3b, out);
}

// round 7
// speedup vs baseline: 1.0831x; 1.0831x over previous
#include <cuda_runtime.h>
#include <cuda_bf16.h>
#include <cstdint>

#define NB 65536
#define SS 5
#define KK 4
#define DD 12
#define HH 48
#define NCB 32        // batch rows per LSTM CTA
#define TPB_L 384     // 48 d  x  8 n-quads
#define SWS 194       // padded ull-stride per d row (1552 B, != 0 mod 128)

typedef unsigned long long ull;

__device__ float g_xbuf[SS * HH * NB];        // [s][feat][n]
__device__ float g_hst[2][(size_t)HH * NB];   // final hidden per dir, [d][n]

// ---------------- helpers ----------------
__device__ __forceinline__ float sigf(float x) {
    return __fdividef(1.0f, 1.0f + __expf(-x));
}
__device__ __forceinline__ float tanhf_(float x) {
    return 1.0f - __fdividef(2.0f, __expf(2.0f * x) + 1.0f);
}
__device__ __forceinline__ ull pack2(float lo, float hi) {
    ull r; asm("mov.b64 %0, {%1, %2};" : "=l"(r) : "f"(lo), "f"(hi)); return r;
}
__device__ __forceinline__ void unpack2(ull v, float& lo, float& hi) {
    asm("mov.b64 {%0, %1}, %2;" : "=f"(lo), "=f"(hi) : "l"(v));
}
__device__ __forceinline__ float red2(ull v) {
    float lo, hi; unpack2(v, lo, hi); return lo + hi;
}
__device__ __forceinline__ void fma2(ull& acc, ull a, ull b) {
    asm("fma.rn.f32x2 %0, %1, %2, %0;" : "+l"(acc) : "l"(a), "l"(b));
}

// ===========================================================================
// Kernel A: GNN message passing (R3 source; regs pinned via min-blocks bound)
// ===========================================================================
__global__ __launch_bounds__(128, 5) void gnn_kernel(
    const float* __restrict__ nf, const float* __restrict__ pos,
    const float* __restrict__ att,
    const float* __restrict__ msgw, const float* __restrict__ msgb,
    const float* __restrict__ gwi, const float* __restrict__ gwh,
    const float* __restrict__ gbi, const float* __restrict__ gbh)
{
    __shared__ float      s_mw[144];
    __shared__ float      s_mb[12];
    __shared__ ulonglong2 sRZ[144];
    __shared__ ull        sN [144];
    __shared__ ull        sBR[12], sBZ[12], sBN[12];

    int tid = threadIdx.x;
    for (int i = tid; i < 144; i += 128) {
        s_mw[i] = msgw[i];
        int d = i / 12, e = i - d * 12;
        ulonglong2 t;
        t.x = pack2(gwi[d * 12 + e],        gwh[d * 12 + e]);
        t.y = pack2(gwi[(12 + d) * 12 + e], gwh[(12 + d) * 12 + e]);
        sRZ[i] = t;
        sN[i]  = pack2(gwi[(24 + d) * 12 + e], gwh[(24 + d) * 12 + e]);
    }
    if (tid < 12) {
        s_mb[tid] = msgb[tid];
        sBR[tid] = pack2(gbi[tid] + gbh[tid], 0.f);
        sBZ[tid] = pack2(gbi[12 + tid] + gbh[12 + tid], 0.f);
        sBN[tid] = pack2(gbi[24 + tid], gbh[24 + tid]);
    }
    __syncthreads();

    int n = blockIdx.x * 128 + tid;
    int s = blockIdx.y;
    int base = n * SS + s;

    float h[KK][DD];
    {
        float t[24];
        const float4* p4 = reinterpret_cast<const float4*>(nf + (size_t)base * 24);
        #pragma unroll
        for (int i = 0; i < 6; i++) {
            float4 v = p4[i];
            t[4*i] = v.x; t[4*i+1] = v.y; t[4*i+2] = v.z; t[4*i+3] = v.w;
        }
        #pragma unroll
        for (int i = 0; i < 24; i++) h[i / 6][i % 6] = t[i];
        const float4* q4 = reinterpret_cast<const float4*>(pos + (size_t)base * 24);
        #pragma unroll
        for (int i = 0; i < 6; i++) {
            float4 v = q4[i];
            t[4*i] = v.x; t[4*i+1] = v.y; t[4*i+2] = v.z; t[4*i+3] = v.w;
        }
        #pragma unroll
        for (int i = 0; i < 24; i++) h[i / 6][6 + i % 6] = t[i];
    }
    float a[KK][KK];
    {
        const float4* a4 = reinterpret_cast<const float4*>(att + (size_t)base * 16);
        #pragma unroll
        for (int k = 0; k < 4; k++) {
            float4 v = a4[k];
            a[k][0] = v.x; a[k][1] = v.y; a[k][2] = v.z; a[k][3] = v.w;
        }
    }

    #pragma unroll 1
    for (int pass = 0; pass < 2; pass++) {
        float hl[48];
        #pragma unroll
        for (int k = 0; k < 4; k++)
            #pragma unroll
            for (int d = 0; d < 12; d++) hl[k * 12 + d] = h[k][d];

        float mv[KK][DD];
        #pragma unroll
        for (int d = 0; d < 12; d++) {
            float ma[4];
            #pragma unroll
            for (int w = 0; w < 4; w++) {
                float acc = s_mb[d];
                #pragma unroll
                for (int e = 0; e < 12; e++) acc += s_mw[d * 12 + e] * h[w][e];
                ma[w] = acc;
            }
            #pragma unroll
            for (int k = 0; k < 4; k++)
                mv[k][d] = a[k][0]*ma[0] + a[k][1]*ma[1] + a[k][2]*ma[2] + a[k][3]*ma[3];
        }

        #pragma unroll
        for (int k = 0; k < 4; k++) {
            ull gk[12];
            #pragma unroll
            for (int e = 0; e < 12; e++) gk[e] = pack2(mv[k][e], h[k][e]);
            float tmpl[12];
            #pragma unroll 1
            for (int d = 0; d < 12; d++) {
                ull aR = sBR[d], aZ = sBZ[d], aN = sBN[d];
                const ulonglong2* wrz = sRZ + d * 12;
                const ull*        wn  = sN  + d * 12;
                #pragma unroll
                for (int e = 0; e < 12; e++) {
                    ulonglong2 w = wrz[e];
                    fma2(aR, w.x, gk[e]);
                    fma2(aZ, w.y, gk[e]);
                    fma2(aN, wn[e], gk[e]);
                }
                float r = sigf(red2(aR));
                float z = sigf(red2(aZ));
                float nlo, nhi; unpack2(aN, nlo, nhi);
                float nn = tanhf_(nlo + r * nhi);
                tmpl[d] = (1.0f - z) * nn + z * hl[k * 12 + d];
            }
            #pragma unroll
            for (int d = 0; d < 12; d++) h[k][d] = tmpl[d];
        }
    }

    #pragma unroll
    for (int k = 0; k < 4; k++)
        #pragma unroll
        for (int d = 0; d < 12; d++)
            g_xbuf[(size_t)(s * HH + d * 4 + k) * NB + n] = h[k][d];
}

// ===========================================================================
// Kernel B: register-tiled bidirectional LSTM.
// Thread (d, q): gates I,F,G,O of dim d for 4 batch rows n = nb+q*4..+3.
// Conflict-free padded weight rows; ping-pong act buffers -> 1 barrier/step.
// Act rows: x buf0 0..23 | x buf1 24..47 | h buf0 48..71 | h buf1 72..95.
// ===========================================================================
#define O_W   0                         /* ull[48*SWS] = 74496 B */
#define O_ACT 74496                     /* ull[96*32]  = 24576 B */
#define O_B   (74496 + 24576)           /* float[192] */
#define SMEM_L (O_B + 768 + 16)

__global__ __launch_bounds__(TPB_L, 2) void lstm_rt_kernel(
    const float* __restrict__ wihF, const float* __restrict__ whhF,
    const float* __restrict__ bihF, const float* __restrict__ bhhF,
    const float* __restrict__ wihB, const float* __restrict__ whhB,
    const float* __restrict__ bihB, const float* __restrict__ bhhB)
{
    extern __shared__ char smc[];
    ull*   sW   = (ull*)(smc + O_W);     // [d][kp][g], row stride SWS
    ull*   sAct = (ull*)(smc + O_ACT);   // [row][n] pairs
    float* sB   = (float*)(smc + O_B);   // [d*4+g]

    int tid = threadIdx.x;
    int d = tid >> 3;       // 0..47
    int q = tid & 7;        // 0..7  -> n = nb + q*4 .. +3
    int nb = blockIdx.x * NCB;

    #pragma unroll 1
    for (int dir = 0; dir < 2; dir++) {
        const float* wih = dir ? wihB : wihF;
        const float* whh = dir ? whhB : whhF;
        const float* bih = dir ? bihB : bihF;
        const float* bhh = dir ? bhhB : bhhF;

        __syncthreads();   // previous dir fully done
        // stage weights (padded rows): sW[dd*SWS + kp*4 + g] = (w[2kp], w[2kp+1])
        for (int i = tid; i < 9216; i += TPB_L) {
            int dd = i / 192;
            int r  = i - dd * 192;
            int kp = r >> 2, g = r & 3;
            int k0 = 2 * kp;
            float w0, w1;
            if (k0 < 48) {
                w0 = wih[(g * 48 + dd) * 48 + k0];
                w1 = wih[(g * 48 + dd) * 48 + k0 + 1];
            } else {
                w0 = whh[(g * 48 + dd) * 48 + (k0 - 48)];
                w1 = whh[(g * 48 + dd) * 48 + (k0 - 47)];
            }
            sW[dd * SWS + r] = pack2(w0, w1);
        }
        for (int i = tid; i < 192; i += TPB_L) {
            int dd = i >> 2, g = i & 3;
            sB[i] = bih[g * 48 + dd] + bhh[g * 48 + dd];
        }
        // zero h buf0 (rows 48..71); stage x for step 0 into x buf0 (rows 0..23)
        {
            int s0 = dir ? (SS - 1) : 0;
            #pragma unroll
            for (int rr = 0; rr < 2; rr++) {
                int i = tid + rr * TPB_L;
                int kp = i >> 5, n = i & 31;
                sAct[(48 + kp) * 32 + n] = 0ull;
                sAct[kp * 32 + n] =
                    pack2(g_xbuf[(size_t)(s0 * HH + 2 * kp) * NB + nb + n],
                          g_xbuf[(size_t)(s0 * HH + 2 * kp + 1) * NB + nb + n]);
            }
        }
        __syncthreads();

        float b0 = sB[d * 4 + 0], b1 = sB[d * 4 + 1];
        float b2 = sB[d * 4 + 2], b3 = sB[d * 4 + 3];
        float c[4] = {0.f, 0.f, 0.f, 0.f};

        #pragma unroll 1
        for (int st = 0; st < SS; st++) {
            int xbase = (st & 1) * 24;           // current x rows; h rows = 48+xbase

            ull acc[4][4];
            #pragma unroll
            for (int g = 0; g < 4; g++)
                #pragma unroll
                for (int u = 0; u < 4; u++) acc[g][u] = 0ull;

            const ulonglong2* wrow = (const ulonglong2*)(sW + d * SWS);
            const ulonglong2* ax = (const ulonglong2*)(sAct + xbase * 32 + q * 4);
            const ulonglong2* ah = (const ulonglong2*)(sAct + (48 + xbase) * 32 + q * 4);

            #pragma unroll 8
            for (int kp = 0; kp < 24; kp++) {
                ulonglong2 wA = wrow[kp * 2];
                ulonglong2 wB = wrow[kp * 2 + 1];
                ulonglong2 aA = ax[kp * 16];
                ulonglong2 aB = ax[kp * 16 + 1];
                fma2(acc[0][0], wA.x, aA.x); fma2(acc[1][0], wA.y, aA.x);
                fma2(acc[2][0], wB.x, aA.x); fma2(acc[3][0], wB.y, aA.x);
                fma2(acc[0][1], wA.x, aA.y); fma2(acc[1][1], wA.y, aA.y);
                fma2(acc[2][1], wB.x, aA.y); fma2(acc[3][1], wB.y, aA.y);
                fma2(acc[0][2], wA.x, aB.x); fma2(acc[1][2], wA.y, aB.x);
                fma2(acc[2][2], wB.x, aB.x); fma2(acc[3][2], wB.y, aB.x);
                fma2(acc[0][3], wA.x, aB.y); fma2(acc[1][3], wA.y, aB.y);
                fma2(acc[2][3], wB.x, aB.y); fma2(acc[3][3], wB.y, aB.y);
            }
            #pragma unroll 8
            for (int kp = 0; kp < 24; kp++) {
                ulonglong2 wA = wrow[48 + kp * 2];
                ulonglong2 wB = wrow[48 + kp * 2 + 1];
                ulonglong2 aA = ah[kp * 16];
                ulonglong2 aB = ah[kp * 16 + 1];
                fma2(acc[0][0], wA.x, aA.x); fma2(acc[1][0], wA.y, aA.x);
                fma2(acc[2][0], wB.x, aA.x); fma2(acc[3][0], wB.y, aA.x);
                fma2(acc[0][1], wA.x, aA.y); fma2(acc[1][1], wA.y, aA.y);
                fma2(acc[2][1], wB.x, aA.y); fma2(acc[3][1], wB.y, aA.y);
                fma2(acc[0][2], wA.x, aB.x); fma2(acc[1][2], wA.y, aB.x);
                fma2(acc[2][2], wB.x, aB.x); fma2(acc[3][2], wB.y, aB.x);
                fma2(acc[0][3], wA.x, aB.y); fma2(acc[1][3], wA.y, aB.y);
                fma2(acc[2][3], wB.x, aB.y); fma2(acc[3][3], wB.y, aB.y);
            }

            float hv[4];
            #pragma unroll
            for (int u = 0; u < 4; u++) {
                float pI = red2(acc[0][u]) + b0;
                float pF = red2(acc[1][u]) + b1;
                float pG = red2(acc[2][u]) + b2;
                float pO = red2(acc[3][u]) + b3;
                float ig = sigf(pI), fg = sigf(pF);
                float gg = tanhf_(pG), og = sigf(pO);
                float cn = fg * c[u] + ig * gg;
                c[u] = cn;
                hv[u] = og * tanhf_(cn);
            }

            if (st < SS - 1) {
                // write h_{t+1} into alt h buf; stage x_{t+1} into alt x buf
                int nbase = ((st + 1) & 1) * 24;
                float* sAf = (float*)sAct;
                int kp_h = 48 + nbase + (d >> 1), par = d & 1;
                #pragma unroll
                for (int u = 0; u < 4; u++)
                    sAf[(kp_h * 32 + q * 4 + u) * 2 + par] = hv[u];

                int sn = dir ? (SS - 2 - st) : (st + 1);
                #pragma unroll
                for (int rr = 0; rr < 2; rr++) {
                    int i = tid + rr * TPB_L;
                    int kp = i >> 5, n = i & 31;
                    sAct[(nbase + kp) * 32 + n] =
                        pack2(g_xbuf[(size_t)(sn * HH + 2 * kp) * NB + nb + n],
                              g_xbuf[(size_t)(sn * HH + 2 * kp + 1) * NB + nb + n]);
                }
            } else {
                float4 o4 = make_float4(hv[0], hv[1], hv[2], hv[3]);
                *(float4*)&g_hst[dir][(size_t)d * NB + nb + q * 4] = o4;
            }
            __syncthreads();
        } // st
    } // dir
}

// ===========================================================================
// Kernel C: MLP head, one thread per n (f32x2 pairs), smem weights
// ===========================================================================
__global__ __launch_bounds__(256) void mlp_kernel(
    const float* __restrict__ e1w, const float* __restrict__ e1b,
    const float* __restrict__ e2w, const float* __restrict__ e2b,
    const float* __restrict__ e3w, const float* __restrict__ e3b,
    float* __restrict__ out)
{
    __shared__ ull   m1p[2304];
    __shared__ float m1b[48], m2[1728], m2b[36], m3[216], m3b[6];

    int tid = threadIdx.x;
    for (int i = tid; i < 2304; i += 256) {
        int ii = i / 48, j = i - ii * 48;
        m1p[i] = pack2(e1w[ii * 96 + j], e1w[ii * 96 + 48 + j]);
    }
    for (int i = tid; i < 1728; i += 256) m2[i] = e2w[i];
    for (int i = tid; i < 216;  i += 256) m3[i] = e3w[i];
    if (tid < 48) m1b[tid] = e1b[tid];
    if (tid < 36) m2b[tid] = e2b[tid];
    if (tid < 6)  m3b[tid] = e3b[tid];
    __syncthreads();

    int n = blockIdx.x * 256 + tid;

    ull av[48];
    #pragma unroll
    for (int j = 0; j < 48; j++)
        av[j] = pack2(g_hst[0][(size_t)j * NB + n], g_hst[1][(size_t)j * NB + n]);

    float x1l[48];
    #pragma unroll 1
    for (int i = 0; i < 48; i++) {
        ull acc = pack2(m1b[i], 0.f);
        const ull* w = m1p + i * 48;
        #pragma unroll
        for (int j = 0; j < 48; j++) fma2(acc, w[j], av[j]);
        x1l[i] = fmaxf(red2(acc), 0.f);
    }
    #pragma unroll
    for (int j = 0; j < 24; j++) av[j] = pack2(x1l[2*j], x1l[2*j+1]);
    const ull* m2p = (const ull*)m2;
    float x2l[36];
    #pragma unroll 1
    for (int i = 0; i < 36; i++) {
        ull acc = pack2(m2b[i], 0.f);
        const ull* w = m2p + i * 24;
        #pragma unroll
        for (int j = 0; j < 24; j++) fma2(acc, w[j], av[j]);
        x2l[i] = fmaxf(red2(acc), 0.f);
    }
    #pragma unroll
    for (int j = 0; j < 18; j++) av[j] = pack2(x2l[2*j], x2l[2*j+1]);
    const ull* m3p = (const ull*)m3;
    #pragma unroll
    for (int cc = 0; cc < 6; cc++) {
        ull acc = pack2(m3b[cc], 0.f);
        const ull* w = m3p + cc * 18;
        #pragma unroll
        for (int j = 0; j < 18; j++) fma2(acc, w[j], av[j]);
        out[(size_t)n * 6 + cc] = red2(acc);
    }
}

// ===========================================================================
extern "C" void kernel_launch(void* const* d_in, const int* in_sizes, int n_in,
                              void* d_out, int out_size)
{
    const float* nf   = (const float*)d_in[0];
    const float* pos  = (const float*)d_in[1];
    const float* att  = (const float*)d_in[2];
    const float* msgw = (const float*)d_in[3];
    const float* msgb = (const float*)d_in[4];
    const float* gwi  = (const float*)d_in[5];
    const float* gwh  = (const float*)d_in[6];
    const float* gbi  = (const float*)d_in[7];
    const float* gbh  = (const float*)d_in[8];
    const float* wihF = (const float*)d_in[9];
    const float* whhF = (const float*)d_in[10];
    const float* bihF = (const float*)d_in[11];
    const float* bhhF = (const float*)d_in[12];
    const float* wihB = (const float*)d_in[13];
    const float* whhB = (const float*)d_in[14];
    const float* bihB = (const float*)d_in[15];
    const float* bhhB = (const float*)d_in[16];
    const float* e1w  = (const float*)d_in[17];
    const float* e1b  = (const float*)d_in[18];
    const float* e2w  = (const float*)d_in[19];
    const float* e2b  = (const float*)d_in[20];
    const float* e3w  = (const float*)d_in[21];
    const float* e3b  = (const float*)d_in[22];
    float* out = (float*)d_out;

    cudaFuncSetAttribute(lstm_rt_kernel,
                         cudaFuncAttributeMaxDynamicSharedMemorySize, SMEM_L);

    dim3 gA(NB / 128, SS);
    gnn_kernel<<<gA, 128>>>(nf, pos, att, msgw, msgb, gwi, gwh, gbi, gbh);
    lstm_rt_kernel<<<NB / NCB, TPB_L, SMEM_L>>>(
        wihF, whhF, bihF, bhhF, wihB, whhB, bihB, bhhB);
    mlp_kernel<<<NB / 256, 256>>>(e1w, e1b, e2w, e2b, e3w, e3b, out);
}

// round 8
// speedup vs baseline: 1.2468x; 1.1511x over previous
#include <cuda_runtime.h>
#include <cuda_bf16.h>
#include <cstdint>

#define NB 65536
#define SS 5
#define KK 4
#define DD 12
#define HH 48
#define NCB 32        // batch rows per LSTM CTA
#define TPB_L 384     // 48 d  x  8 n-quads
#define SWS 194       // padded ull-stride per d row (1552 B, != 0 mod 128)

typedef unsigned long long ull;

__device__ float g_xbuf[SS * HH * NB];        // [s][feat][n]
__device__ float g_hst[2][(size_t)HH * NB];   // final hidden per dir, [d][n]

// ---------------- helpers ----------------
__device__ __forceinline__ float sigf(float x) {
    return __fdividef(1.0f, 1.0f + __expf(-x));
}
__device__ __forceinline__ float tanhf_(float x) {
    return 1.0f - __fdividef(2.0f, __expf(2.0f * x) + 1.0f);
}
__device__ __forceinline__ ull pack2(float lo, float hi) {
    ull r; asm("mov.b64 %0, {%1, %2};" : "=l"(r) : "f"(lo), "f"(hi)); return r;
}
__device__ __forceinline__ void unpack2(ull v, float& lo, float& hi) {
    asm("mov.b64 {%0, %1}, %2;" : "=f"(lo), "=f"(hi) : "l"(v));
}
__device__ __forceinline__ float red2(ull v) {
    float lo, hi; unpack2(v, lo, hi); return lo + hi;
}
__device__ __forceinline__ void fma2(ull& acc, ull a, ull b) {
    asm("fma.rn.f32x2 %0, %1, %2, %0;" : "+l"(acc) : "l"(a), "l"(b));
}

// n (0..31) -> ull position within a 32-ull act row (conflict-free halves)
__device__ __forceinline__ int act_pos(int n) {
    int q = n >> 2, u = n & 3;
    return (u < 2) ? (q * 2 + u) : (16 + q * 2 + u - 2);
}

// ===========================================================================
// Kernel A: GNN message passing (regs capped at 128 via (128,4))
// ===========================================================================
__global__ __launch_bounds__(128, 4) void gnn_kernel(
    const float* __restrict__ nf, const float* __restrict__ pos,
    const float* __restrict__ att,
    const float* __restrict__ msgw, const float* __restrict__ msgb,
    const float* __restrict__ gwi, const float* __restrict__ gwh,
    const float* __restrict__ gbi, const float* __restrict__ gbh)
{
    __shared__ float      s_mw[144];
    __shared__ float      s_mb[12];
    __shared__ ulonglong2 sRZ[144];
    __shared__ ull        sN [144];
    __shared__ ull        sBR[12], sBZ[12], sBN[12];

    int tid = threadIdx.x;
    for (int i = tid; i < 144; i += 128) {
        s_mw[i] = msgw[i];
        int d = i / 12, e = i - d * 12;
        ulonglong2 t;
        t.x = pack2(gwi[d * 12 + e],        gwh[d * 12 + e]);
        t.y = pack2(gwi[(12 + d) * 12 + e], gwh[(12 + d) * 12 + e]);
        sRZ[i] = t;
        sN[i]  = pack2(gwi[(24 + d) * 12 + e], gwh[(24 + d) * 12 + e]);
    }
    if (tid < 12) {
        s_mb[tid] = msgb[tid];
        sBR[tid] = pack2(gbi[tid] + gbh[tid], 0.f);
        sBZ[tid] = pack2(gbi[12 + tid] + gbh[12 + tid], 0.f);
        sBN[tid] = pack2(gbi[24 + tid], gbh[24 + tid]);
    }
    __syncthreads();

    int n = blockIdx.x * 128 + tid;
    int s = blockIdx.y;
    int base = n * SS + s;

    float h[KK][DD];
    {
        float t[24];
        const float4* p4 = reinterpret_cast<const float4*>(nf + (size_t)base * 24);
        #pragma unroll
        for (int i = 0; i < 6; i++) {
            float4 v = p4[i];
            t[4*i] = v.x; t[4*i+1] = v.y; t[4*i+2] = v.z; t[4*i+3] = v.w;
        }
        #pragma unroll
        for (int i = 0; i < 24; i++) h[i / 6][i % 6] = t[i];
        const float4* q4 = reinterpret_cast<const float4*>(pos + (size_t)base * 24);
        #pragma unroll
        for (int i = 0; i < 6; i++) {
            float4 v = q4[i];
            t[4*i] = v.x; t[4*i+1] = v.y; t[4*i+2] = v.z; t[4*i+3] = v.w;
        }
        #pragma unroll
        for (int i = 0; i < 24; i++) h[i / 6][6 + i % 6] = t[i];
    }
    float a[KK][KK];
    {
        const float4* a4 = reinterpret_cast<const float4*>(att + (size_t)base * 16);
        #pragma unroll
        for (int k = 0; k < 4; k++) {
            float4 v = a4[k];
            a[k][0] = v.x; a[k][1] = v.y; a[k][2] = v.z; a[k][3] = v.w;
        }
    }

    #pragma unroll 1
    for (int pass = 0; pass < 2; pass++) {
        float hl[48];
        #pragma unroll
        for (int k = 0; k < 4; k++)
            #pragma unroll
            for (int d = 0; d < 12; d++) hl[k * 12 + d] = h[k][d];

        float mv[KK][DD];
        #pragma unroll
        for (int d = 0; d < 12; d++) {
            float ma[4];
            #pragma unroll
            for (int w = 0; w < 4; w++) {
                float acc = s_mb[d];
                #pragma unroll
                for (int e = 0; e < 12; e++) acc += s_mw[d * 12 + e] * h[w][e];
                ma[w] = acc;
            }
            #pragma unroll
            for (int k = 0; k < 4; k++)
                mv[k][d] = a[k][0]*ma[0] + a[k][1]*ma[1] + a[k][2]*ma[2] + a[k][3]*ma[3];
        }

        #pragma unroll
        for (int k = 0; k < 4; k++) {
            ull gk[12];
            #pragma unroll
            for (int e = 0; e < 12; e++) gk[e] = pack2(mv[k][e], h[k][e]);
            float tmpl[12];
            #pragma unroll 1
            for (int d = 0; d < 12; d++) {
                ull aR = sBR[d], aZ = sBZ[d], aN = sBN[d];
                const ulonglong2* wrz = sRZ + d * 12;
                const ull*        wn  = sN  + d * 12;
                #pragma unroll
                for (int e = 0; e < 12; e++) {
                    ulonglong2 w = wrz[e];
                    fma2(aR, w.x, gk[e]);
                    fma2(aZ, w.y, gk[e]);
                    fma2(aN, wn[e], gk[e]);
                }
                float r = sigf(red2(aR));
                float z = sigf(red2(aZ));
                float nlo, nhi; unpack2(aN, nlo, nhi);
                float nn = tanhf_(nlo + r * nhi);
                tmpl[d] = (1.0f - z) * nn + z * hl[k * 12 + d];
            }
            #pragma unroll
            for (int d = 0; d < 12; d++) h[k][d] = tmpl[d];
        }
    }

    #pragma unroll
    for (int k = 0; k < 4; k++)
        #pragma unroll
        for (int d = 0; d < 12; d++)
            g_xbuf[(size_t)(s * HH + d * 4 + k) * NB + n] = h[k][d];
}

// ===========================================================================
// Kernel B: register-tiled bidirectional LSTM.
// Thread (d, q): gates I,F,G,O of dim d for 4 batch rows.
// (384,1): no accumulator spills. Act rows use split-half layout so each
// activation LDS.128 spans exactly 128B across the 8 q-lanes (1 wavefront).
// ===========================================================================
#define O_W   0                         /* ull[48*SWS] = 74496 B */
#define O_ACT 74496                     /* ull[96*32]  = 24576 B */
#define O_B   (74496 + 24576)           /* float[192] */
#define SMEM_L (O_B + 768 + 16)

__global__ __launch_bounds__(TPB_L, 1) void lstm_rt_kernel(
    const float* __restrict__ wihF, const float* __restrict__ whhF,
    const float* __restrict__ bihF, const float* __restrict__ bhhF,
    const float* __restrict__ wihB, const float* __restrict__ whhB,
    const float* __restrict__ bihB, const float* __restrict__ bhhB)
{
    extern __shared__ char smc[];
    ull*   sW   = (ull*)(smc + O_W);     // [d][kp][g], row stride SWS
    ull*   sAct = (ull*)(smc + O_ACT);   // [row][32] with act_pos layout
    float* sB   = (float*)(smc + O_B);   // [d*4+g]

    int tid = threadIdx.x;
    int d = tid >> 3;       // 0..47
    int q = tid & 7;        // 0..7
    int nb = blockIdx.x * NCB;

    #pragma unroll 1
    for (int dir = 0; dir < 2; dir++) {
        const float* wih = dir ? wihB : wihF;
        const float* whh = dir ? whhB : whhF;
        const float* bih = dir ? bihB : bihF;
        const float* bhh = dir ? bhhB : bhhF;

        __syncthreads();   // previous dir fully done
        for (int i = tid; i < 9216; i += TPB_L) {
            int dd = i / 192;
            int r  = i - dd * 192;
            int kp = r >> 2, g = r & 3;
            int k0 = 2 * kp;
            float w0, w1;
            if (k0 < 48) {
                w0 = wih[(g * 48 + dd) * 48 + k0];
                w1 = wih[(g * 48 + dd) * 48 + k0 + 1];
            } else {
                w0 = whh[(g * 48 + dd) * 48 + (k0 - 48)];
                w1 = whh[(g * 48 + dd) * 48 + (k0 - 47)];
            }
            sW[dd * SWS + r] = pack2(w0, w1);
        }
        for (int i = tid; i < 192; i += TPB_L) {
            int dd = i >> 2, g = i & 3;
            sB[i] = bih[g * 48 + dd] + bhh[g * 48 + dd];
        }
        // zero h buf0 (rows 48..71); stage x step0 into x buf0 (rows 0..23)
        {
            int s0 = dir ? (SS - 1) : 0;
            #pragma unroll
            for (int rr = 0; rr < 2; rr++) {
                int i = tid + rr * TPB_L;
                int kp = i >> 5, n = i & 31;
                int p = act_pos(n);
                sAct[(48 + kp) * 32 + p] = 0ull;
                sAct[kp * 32 + p] =
                    pack2(g_xbuf[(size_t)(s0 * HH + 2 * kp) * NB + nb + n],
                          g_xbuf[(size_t)(s0 * HH + 2 * kp + 1) * NB + nb + n]);
            }
        }
        __syncthreads();

        float b0 = sB[d * 4 + 0], b1 = sB[d * 4 + 1];
        float b2 = sB[d * 4 + 2], b3 = sB[d * 4 + 3];
        float c[4] = {0.f, 0.f, 0.f, 0.f};

        #pragma unroll 1
        for (int st = 0; st < SS; st++) {
            int xbase = (st & 1) * 24;

            ull acc[4][4];
            #pragma unroll
            for (int g = 0; g < 4; g++)
                #pragma unroll
                for (int u = 0; u < 4; u++) acc[g][u] = 0ull;

            const ulonglong2* wrow = (const ulonglong2*)(sW + d * SWS);
            const ull* axr = sAct + xbase * 32;
            const ull* ahr = sAct + (48 + xbase) * 32;

            #pragma unroll 8
            for (int kp = 0; kp < 24; kp++) {
                ulonglong2 wA = wrow[kp * 2];
                ulonglong2 wB = wrow[kp * 2 + 1];
                ulonglong2 aA = *(const ulonglong2*)(axr + kp * 32 + q * 2);
                ulonglong2 aB = *(const ulonglong2*)(axr + kp * 32 + 16 + q * 2);
                fma2(acc[0][0], wA.x, aA.x); fma2(acc[1][0], wA.y, aA.x);
                fma2(acc[2][0], wB.x, aA.x); fma2(acc[3][0], wB.y, aA.x);
                fma2(acc[0][1], wA.x, aA.y); fma2(acc[1][1], wA.y, aA.y);
                fma2(acc[2][1], wB.x, aA.y); fma2(acc[3][1], wB.y, aA.y);
                fma2(acc[0][2], wA.x, aB.x); fma2(acc[1][2], wA.y, aB.x);
                fma2(acc[2][2], wB.x, aB.x); fma2(acc[3][2], wB.y, aB.x);
                fma2(acc[0][3], wA.x, aB.y); fma2(acc[1][3], wA.y, aB.y);
                fma2(acc[2][3], wB.x, aB.y); fma2(acc[3][3], wB.y, aB.y);
            }
            #pragma unroll 8
            for (int kp = 0; kp < 24; kp++) {
                ulonglong2 wA = wrow[48 + kp * 2];
                ulonglong2 wB = wrow[48 + kp * 2 + 1];
                ulonglong2 aA = *(const ulonglong2*)(ahr + kp * 32 + q * 2);
                ulonglong2 aB = *(const ulonglong2*)(ahr + kp * 32 + 16 + q * 2);
                fma2(acc[0][0], wA.x, aA.x); fma2(acc[1][0], wA.y, aA.x);
                fma2(acc[2][0], wB.x, aA.x); fma2(acc[3][0], wB.y, aA.x);
                fma2(acc[0][1], wA.x, aA.y); fma2(acc[1][1], wA.y, aA.y);
                fma2(acc[2][1], wB.x, aA.y); fma2(acc[3][1], wB.y, aA.y);
                fma2(acc[0][2], wA.x, aB.x); fma2(acc[1][2], wA.y, aB.x);
                fma2(acc[2][2], wB.x, aB.x); fma2(acc[3][2], wB.y, aB.x);
                fma2(acc[0][3], wA.x, aB.y); fma2(acc[1][3], wA.y, aB.y);
                fma2(acc[2][3], wB.x, aB.y); fma2(acc[3][3], wB.y, aB.y);
            }

            // n of acc[.][u]: aA -> q*4+0, q*4+1 ; aB -> q*4+2, q*4+3
            float hv[4];
            #pragma unroll
            for (int u = 0; u < 4; u++) {
                float pI = red2(acc[0][u]) + b0;
                float pF = red2(acc[1][u]) + b1;
                float pG = red2(acc[2][u]) + b2;
                float pO = red2(acc[3][u]) + b3;
                float ig = sigf(pI), fg = sigf(pF);
                float gg = tanhf_(pG), og = sigf(pO);
                float cn = fg * c[u] + ig * gg;
                c[u] = cn;
                hv[u] = og * tanhf_(cn);
            }

            if (st < SS - 1) {
                int nbase = ((st + 1) & 1) * 24;
                float* sAf = (float*)sAct;
                int kp_h = 48 + nbase + (d >> 1), par = d & 1;
                #pragma unroll
                for (int u = 0; u < 4; u++) {
                    int p = act_pos(q * 4 + u);
                    sAf[(kp_h * 32 + p) * 2 + par] = hv[u];
                }

                int sn = dir ? (SS - 2 - st) : (st + 1);
                #pragma unroll
                for (int rr = 0; rr < 2; rr++) {
                    int i = tid + rr * TPB_L;
                    int kp = i >> 5, n = i & 31;
                    sAct[(nbase + kp) * 32 + act_pos(n)] =
                        pack2(g_xbuf[(size_t)(sn * HH + 2 * kp) * NB + nb + n],
                              g_xbuf[(size_t)(sn * HH + 2 * kp + 1) * NB + nb + n]);
                }
            } else {
                float4 o4 = make_float4(hv[0], hv[1], hv[2], hv[3]);
                *(float4*)&g_hst[dir][(size_t)d * NB + nb + q * 4] = o4;
            }
            __syncthreads();
        } // st
    } // dir
}

// ===========================================================================
// Kernel C: MLP head, one thread per n (f32x2 pairs), smem weights
// ===========================================================================
__global__ __launch_bounds__(256) void mlp_kernel(
    const float* __restrict__ e1w, const float* __restrict__ e1b,
    const float* __restrict__ e2w, const float* __restrict__ e2b,
    const float* __restrict__ e3w, const float* __restrict__ e3b,
    float* __restrict__ out)
{
    __shared__ ull   m1p[2304];
    __shared__ float m1b[48], m2[1728], m2b[36], m3[216], m3b[6];

    int tid = threadIdx.x;
    for (int i = tid; i < 2304; i += 256) {
        int ii = i / 48, j = i - ii * 48;
        m1p[i] = pack2(e1w[ii * 96 + j], e1w[ii * 96 + 48 + j]);
    }
    for (int i = tid; i < 1728; i += 256) m2[i] = e2w[i];
    for (int i = tid; i < 216;  i += 256) m3[i] = e3w[i];
    if (tid < 48) m1b[tid] = e1b[tid];
    if (tid < 36) m2b[tid] = e2b[tid];
    if (tid < 6)  m3b[tid] = e3b[tid];
    __syncthreads();

    int n = blockIdx.x * 256 + tid;

    ull av[48];
    #pragma unroll
    for (int j = 0; j < 48; j++)
        av[j] = pack2(g_hst[0][(size_t)j * NB + n], g_hst[1][(size_t)j * NB + n]);

    float x1l[48];
    #pragma unroll 1
    for (int i = 0; i < 48; i++) {
        ull acc = pack2(m1b[i], 0.f);
        const ull* w = m1p + i * 48;
        #pragma unroll
        for (int j = 0; j < 48; j++) fma2(acc, w[j], av[j]);
        x1l[i] = fmaxf(red2(acc), 0.f);
    }
    #pragma unroll
    for (int j = 0; j < 24; j++) av[j] = pack2(x1l[2*j], x1l[2*j+1]);
    const ull* m2p = (const ull*)m2;
    float x2l[36];
    #pragma unroll 1
    for (int i = 0; i < 36; i++) {
        ull acc = pack2(m2b[i], 0.f);
        const ull* w = m2p + i * 24;
        #pragma unroll
        for (int j = 0; j < 24; j++) fma2(acc, w[j], av[j]);
        x2l[i] = fmaxf(red2(acc), 0.f);
    }
    #pragma unroll
    for (int j = 0; j < 18; j++) av[j] = pack2(x2l[2*j], x2l[2*j+1]);
    const ull* m3p = (const ull*)m3;
    #pragma unroll
    for (int cc = 0; cc < 6; cc++) {
        ull acc = pack2(m3b[cc], 0.f);
        const ull* w = m3p + cc * 18;
        #pragma unroll
        for (int j = 0; j < 18; j++) fma2(acc, w[j], av[j]);
        out[(size_t)n * 6 + cc] = red2(acc);
    }
}

// ===========================================================================
extern "C" void kernel_launch(void* const* d_in, const int* in_sizes, int n_in,
                              void* d_out, int out_size)
{
    const float* nf   = (const float*)d_in[0];
    const float* pos  = (const float*)d_in[1];
    const float* att  = (const float*)d_in[2];
    const float* msgw = (const float*)d_in[3];
    const float* msgb = (const float*)d_in[4];
    const float* gwi  = (const float*)d_in[5];
    const float* gwh  = (const float*)d_in[6];
    const float* gbi  = (const float*)d_in[7];
    const float* gbh  = (const float*)d_in[8];
    const float* wihF = (const float*)d_in[9];
    const float* whhF = (const float*)d_in[10];
    const float* bihF = (const float*)d_in[11];
    const float* bhhF = (const float*)d_in[12];
    const float* wihB = (const float*)d_in[13];
    const float* whhB = (const float*)d_in[14];
    const float* bihB = (const float*)d_in[15];
    const float* bhhB = (const float*)d_in[16];
    const float* e1w  = (const float*)d_in[17];
    const float* e1b  = (const float*)d_in[18];
    const float* e2w  = (const float*)d_in[19];
    const float* e2b  = (const float*)d_in[20];
    const float* e3w  = (const float*)d_in[21];
    const float* e3b  = (const float*)d_in[22];
    float* out = (float*)d_out;

    cudaFuncSetAttribute(lstm_rt_kernel,
                         cudaFuncAttributeMaxDynamicSharedMemorySize, SMEM_L);

    dim3 gA(NB / 128, SS);
    gnn_kernel<<<gA, 128>>>(nf, pos, att, msgw, msgb, gwi, gwh, gbi, gbh);
    lstm_rt_kernel<<<NB / NCB, TPB_L, SMEM_L>>>(
        wihF, whhF, bihF, bhhF, wihB, whhB, bihB, bhhB);
    mlp_kernel<<<NB / 256, 256>>>(e1w, e1b, e2w, e2b, e3w, e3b, out);
}

// round 12
// speedup vs baseline: 1.3008x; 1.0433x over previous
#include <cuda_runtime.h>
#include <cuda_bf16.h>
#include <cstdint>

#define NB 65536
#define SS 5
#define KK 4
#define DD 12
#define HH 48
#define NCB 32        // batch rows per LSTM CTA
#define TPB_L 384     // 48 d  x  8 n-quads
#define SWS 194       // padded ull-stride per d row (1552 B, != 0 mod 128)

typedef unsigned long long ull;

__device__ float g_xbuf[SS * HH * NB];        // [s][feat][n]
__device__ float g_hst[2][(size_t)HH * NB];   // final hidden per dir, [d][n]

// ---------------- helpers ----------------
__device__ __forceinline__ float sigf(float x) {
    return __fdividef(1.0f, 1.0f + __expf(-x));
}
__device__ __forceinline__ float tanhf_(float x) {
    return 1.0f - __fdividef(2.0f, __expf(2.0f * x) + 1.0f);
}
__device__ __forceinline__ ull pack2(float lo, float hi) {
    ull r; asm("mov.b64 %0, {%1, %2};" : "=l"(r) : "f"(lo), "f"(hi)); return r;
}
__device__ __forceinline__ void unpack2(ull v, float& lo, float& hi) {
    asm("mov.b64 {%0, %1}, %2;" : "=f"(lo), "=f"(hi) : "l"(v));
}
__device__ __forceinline__ float red2(ull v) {
    float lo, hi; unpack2(v, lo, hi); return lo + hi;
}
__device__ __forceinline__ void fma2(ull& acc, ull a, ull b) {
    asm("fma.rn.f32x2 %0, %1, %2, %0;" : "+l"(acc) : "l"(a), "l"(b));
}

// n (0..31) -> ull position within a 32-ull act row (conflict-free halves)
__device__ __forceinline__ int act_pos(int n) {
    int q = n >> 2, u = n & 3;
    return (u < 2) ? (q * 2 + u) : (16 + q * 2 + u - 2);
}

// ===========================================================================
// Kernel A: GNN message passing (unbounded regs — fastest measured variant)
// ===========================================================================
__global__ __launch_bounds__(128) void gnn_kernel(
    const float* __restrict__ nf, const float* __restrict__ pos,
    const float* __restrict__ att,
    const float* __restrict__ msgw, const float* __restrict__ msgb,
    const float* __restrict__ gwi, const float* __restrict__ gwh,
    const float* __restrict__ gbi, const float* __restrict__ gbh)
{
    __shared__ float      s_mw[144];
    __shared__ float      s_mb[12];
    __shared__ ulonglong2 sRZ[144];
    __shared__ ull        sN [144];
    __shared__ ull        sBR[12], sBZ[12], sBN[12];

    int tid = threadIdx.x;
    for (int i = tid; i < 144; i += 128) {
        s_mw[i] = msgw[i];
        int d = i / 12, e = i - d * 12;
        ulonglong2 t;
        t.x = pack2(gwi[d * 12 + e],        gwh[d * 12 + e]);
        t.y = pack2(gwi[(12 + d) * 12 + e], gwh[(12 + d) * 12 + e]);
        sRZ[i] = t;
        sN[i]  = pack2(gwi[(24 + d) * 12 + e], gwh[(24 + d) * 12 + e]);
    }
    if (tid < 12) {
        s_mb[tid] = msgb[tid];
        sBR[tid] = pack2(gbi[tid] + gbh[tid], 0.f);
        sBZ[tid] = pack2(gbi[12 + tid] + gbh[12 + tid], 0.f);
        sBN[tid] = pack2(gbi[24 + tid], gbh[24 + tid]);
    }
    __syncthreads();

    int n = blockIdx.x * 128 + tid;
    int s = blockIdx.y;
    int base = n * SS + s;

    float h[KK][DD];
    {
        float t[24];
        const float4* p4 = reinterpret_cast<const float4*>(nf + (size_t)base * 24);
        #pragma unroll
        for (int i = 0; i < 6; i++) {
            float4 v = p4[i];
            t[4*i] = v.x; t[4*i+1] = v.y; t[4*i+2] = v.z; t[4*i+3] = v.w;
        }
        #pragma unroll
        for (int i = 0; i < 24; i++) h[i / 6][i % 6] = t[i];
        const float4* q4 = reinterpret_cast<const float4*>(pos + (size_t)base * 24);
        #pragma unroll
        for (int i = 0; i < 6; i++) {
            float4 v = q4[i];
            t[4*i] = v.x; t[4*i+1] = v.y; t[4*i+2] = v.z; t[4*i+3] = v.w;
        }
        #pragma unroll
        for (int i = 0; i < 24; i++) h[i / 6][6 + i % 6] = t[i];
    }
    float a[KK][KK];
    {
        const float4* a4 = reinterpret_cast<const float4*>(att + (size_t)base * 16);
        #pragma unroll
        for (int k = 0; k < 4; k++) {
            float4 v = a4[k];
            a[k][0] = v.x; a[k][1] = v.y; a[k][2] = v.z; a[k][3] = v.w;
        }
    }

    #pragma unroll 1
    for (int pass = 0; pass < 2; pass++) {
        float hl[48];
        #pragma unroll
        for (int k = 0; k < 4; k++)
            #pragma unroll
            for (int d = 0; d < 12; d++) hl[k * 12 + d] = h[k][d];

        float mv[KK][DD];
        #pragma unroll
        for (int d = 0; d < 12; d++) {
            float ma[4];
            #pragma unroll
            for (int w = 0; w < 4; w++) {
                float acc = s_mb[d];
                #pragma unroll
                for (int e = 0; e < 12; e++) acc += s_mw[d * 12 + e] * h[w][e];
                ma[w] = acc;
            }
            #pragma unroll
            for (int k = 0; k < 4; k++)
                mv[k][d] = a[k][0]*ma[0] + a[k][1]*ma[1] + a[k][2]*ma[2] + a[k][3]*ma[3];
        }

        #pragma unroll
        for (int k = 0; k < 4; k++) {
            ull gk[12];
            #pragma unroll
            for (int e = 0; e < 12; e++) gk[e] = pack2(mv[k][e], h[k][e]);
            float tmpl[12];
            #pragma unroll 1
            for (int d = 0; d < 12; d++) {
                ull aR = sBR[d], aZ = sBZ[d], aN = sBN[d];
                const ulonglong2* wrz = sRZ + d * 12;
                const ull*        wn  = sN  + d * 12;
                #pragma unroll
                for (int e = 0; e < 12; e++) {
                    ulonglong2 w = wrz[e];
                    fma2(aR, w.x, gk[e]);
                    fma2(aZ, w.y, gk[e]);
                    fma2(aN, wn[e], gk[e]);
                }
                float r = sigf(red2(aR));
                float z = sigf(red2(aZ));
                float nlo, nhi; unpack2(aN, nlo, nhi);
                float nn = tanhf_(nlo + r * nhi);
                tmpl[d] = (1.0f - z) * nn + z * hl[k * 12 + d];
            }
            #pragma unroll
            for (int d = 0; d < 12; d++) h[k][d] = tmpl[d];
        }
    }

    #pragma unroll
    for (int k = 0; k < 4; k++)
        #pragma unroll
        for (int d = 0; d < 12; d++)
            g_xbuf[(size_t)(s * HH + d * 4 + k) * NB + n] = h[k][d];
}

// ===========================================================================
// Kernel B: register-tiled bidirectional LSTM (R8-passing version +
// x prefetch-staging moved to the TOP of each step).
// ===========================================================================
#define O_W   0                         /* ull[48*SWS] = 74496 B */
#define O_ACT 74496                     /* ull[96*32]  = 24576 B */
#define O_B   (74496 + 24576)           /* float[192] */
#define SMEM_L (O_B + 768 + 16)

__global__ __launch_bounds__(TPB_L, 1) void lstm_rt_kernel(
    const float* __restrict__ wihF, const float* __restrict__ whhF,
    const float* __restrict__ bihF, const float* __restrict__ bhhF,
    const float* __restrict__ wihB, const float* __restrict__ whhB,
    const float* __restrict__ bihB, const float* __restrict__ bhhB)
{
    extern __shared__ char smc[];
    ull*   sW   = (ull*)(smc + O_W);     // [d][kp][g], row stride SWS
    ull*   sAct = (ull*)(smc + O_ACT);   // [row][32] with act_pos layout
    float* sB   = (float*)(smc + O_B);   // [d*4+g]

    int tid = threadIdx.x;
    int d = tid >> 3;       // 0..47
    int q = tid & 7;        // 0..7
    int nb = blockIdx.x * NCB;

    #pragma unroll 1
    for (int dir = 0; dir < 2; dir++) {
        const float* wih = dir ? wihB : wihF;
        const float* whh = dir ? whhB : whhF;
        const float* bih = dir ? bihB : bihF;
        const float* bhh = dir ? bhhB : bhhF;

        __syncthreads();   // previous dir fully done
        for (int i = tid; i < 9216; i += TPB_L) {
            int dd = i / 192;
            int r  = i - dd * 192;
            int kp = r >> 2, g = r & 3;
            int k0 = 2 * kp;
            float w0, w1;
            if (k0 < 48) {
                w0 = wih[(g * 48 + dd) * 48 + k0];
                w1 = wih[(g * 48 + dd) * 48 + k0 + 1];
            } else {
                w0 = whh[(g * 48 + dd) * 48 + (k0 - 48)];
                w1 = whh[(g * 48 + dd) * 48 + (k0 - 47)];
            }
            sW[dd * SWS + r] = pack2(w0, w1);
        }
        for (int i = tid; i < 192; i += TPB_L) {
            int dd = i >> 2, g = i & 3;
            sB[i] = bih[g * 48 + dd] + bhh[g * 48 + dd];
        }
        // zero h buf0 (rows 48..71); stage x step0 into x buf0 (rows 0..23)
        {
            int s0 = dir ? (SS - 1) : 0;
            #pragma unroll
            for (int rr = 0; rr < 2; rr++) {
                int i = tid + rr * TPB_L;
                int kp = i >> 5, n = i & 31;
                int p = act_pos(n);
                sAct[(48 + kp) * 32 + p] = 0ull;
                sAct[kp * 32 + p] =
                    pack2(g_xbuf[(size_t)(s0 * HH + 2 * kp) * NB + nb + n],
                          g_xbuf[(size_t)(s0 * HH + 2 * kp + 1) * NB + nb + n]);
            }
        }
        __syncthreads();

        float b0 = sB[d * 4 + 0], b1 = sB[d * 4 + 1];
        float b2 = sB[d * 4 + 2], b3 = sB[d * 4 + 3];
        float c[4] = {0.f, 0.f, 0.f, 0.f};

        #pragma unroll 1
        for (int st = 0; st < SS; st++) {
            int xbase = (st & 1) * 24;

            // prefetch-stage x for step st+1 into the free ping-pong buffer.
            // Safe: that buffer's readers finished at the end of step st-1
            // (end-of-step barrier); its h region is written after the epilogue.
            if (st < SS - 1) {
                int nbase = ((st + 1) & 1) * 24;
                int sn = dir ? (SS - 2 - st) : (st + 1);
                #pragma unroll
                for (int rr = 0; rr < 2; rr++) {
                    int i = tid + rr * TPB_L;
                    int kp = i >> 5, n = i & 31;
                    sAct[(nbase + kp) * 32 + act_pos(n)] =
                        pack2(g_xbuf[(size_t)(sn * HH + 2 * kp) * NB + nb + n],
                              g_xbuf[(size_t)(sn * HH + 2 * kp + 1) * NB + nb + n]);
                }
            }

            ull acc[4][4];
            #pragma unroll
            for (int g = 0; g < 4; g++)
                #pragma unroll
                for (int u = 0; u < 4; u++) acc[g][u] = 0ull;

            const ulonglong2* wrow = (const ulonglong2*)(sW + d * SWS);
            const ull* axr = sAct + xbase * 32;
            const ull* ahr = sAct + (48 + xbase) * 32;

            #pragma unroll 8
            for (int kp = 0; kp < 24; kp++) {
                ulonglong2 wA = wrow[kp * 2];
                ulonglong2 wB = wrow[kp * 2 + 1];
                ulonglong2 aA = *(const ulonglong2*)(axr + kp * 32 + q * 2);
                ulonglong2 aB = *(const ulonglong2*)(axr + kp * 32 + 16 + q * 2);
                fma2(acc[0][0], wA.x, aA.x); fma2(acc[1][0], wA.y, aA.x);
                fma2(acc[2][0], wB.x, aA.x); fma2(acc[3][0], wB.y, aA.x);
                fma2(acc[0][1], wA.x, aA.y); fma2(acc[1][1], wA.y, aA.y);
                fma2(acc[2][1], wB.x, aA.y); fma2(acc[3][1], wB.y, aA.y);
                fma2(acc[0][2], wA.x, aB.x); fma2(acc[1][2], wA.y, aB.x);
                fma2(acc[2][2], wB.x, aB.x); fma2(acc[3][2], wB.y, aB.x);
                fma2(acc[0][3], wA.x, aB.y); fma2(acc[1][3], wA.y, aB.y);
                fma2(acc[2][3], wB.x, aB.y); fma2(acc[3][3], wB.y, aB.y);
            }
            #pragma unroll 8
            for (int kp = 0; kp < 24; kp++) {
                ulonglong2 wA = wrow[48 + kp * 2];
                ulonglong2 wB = wrow[48 + kp * 2 + 1];
                ulonglong2 aA = *(const ulonglong2*)(ahr + kp * 32 + q * 2);
                ulonglong2 aB = *(const ulonglong2*)(ahr + kp * 32 + 16 + q * 2);
                fma2(acc[0][0], wA.x, aA.x); fma2(acc[1][0], wA.y, aA.x);
                fma2(acc[2][0], wB.x, aA.x); fma2(acc[3][0], wB.y, aA.x);
                fma2(acc[0][1], wA.x, aA.y); fma2(acc[1][1], wA.y, aA.y);
                fma2(acc[2][1], wB.x, aA.y); fma2(acc[3][1], wB.y, aA.y);
                fma2(acc[0][2], wA.x, aB.x); fma2(acc[1][2], wA.y, aB.x);
                fma2(acc[2][2], wB.x, aB.x); fma2(acc[3][2], wB.y, aB.x);
                fma2(acc[0][3], wA.x, aB.y); fma2(acc[1][3], wA.y, aB.y);
                fma2(acc[2][3], wB.x, aB.y); fma2(acc[3][3], wB.y, aB.y);
            }

            float hv[4];
            #pragma unroll
            for (int u = 0; u < 4; u++) {
                float pI = red2(acc[0][u]) + b0;
                float pF = red2(acc[1][u]) + b1;
                float pG = red2(acc[2][u]) + b2;
                float pO = red2(acc[3][u]) + b3;
                float ig = sigf(pI), fg = sigf(pF);
                float gg = tanhf_(pG), og = sigf(pO);
                float cn = fg * c[u] + ig * gg;
                c[u] = cn;
                hv[u] = og * tanhf_(cn);
            }

            if (st < SS - 1) {
                int nbase = ((st + 1) & 1) * 24;
                float* sAf = (float*)sAct;
                int kp_h = 48 + nbase + (d >> 1), par = d & 1;
                #pragma unroll
                for (int u = 0; u < 4; u++) {
                    int p = act_pos(q * 4 + u);
                    sAf[(kp_h * 32 + p) * 2 + par] = hv[u];
                }
            } else {
                float4 o4 = make_float4(hv[0], hv[1], hv[2], hv[3]);
                *(float4*)&g_hst[dir][(size_t)d * NB + nb + q * 4] = o4;
            }
            __syncthreads();
        } // st
    } // dir
}

// ===========================================================================
// Kernel C: MLP head, one thread per n (f32x2 pairs), smem weights
// ===========================================================================
__global__ __launch_bounds__(256) void mlp_kernel(
    const float* __restrict__ e1w, const float* __restrict__ e1b,
    const float* __restrict__ e2w, const float* __restrict__ e2b,
    const float* __restrict__ e3w, const float* __restrict__ e3b,
    float* __restrict__ out)
{
    __shared__ ull   m1p[2304];
    __shared__ float m1b[48], m2[1728], m2b[36], m3[216], m3b[6];

    int tid = threadIdx.x;
    for (int i = tid; i < 2304; i += 256) {
        int ii = i / 48, j = i - ii * 48;
        m1p[i] = pack2(e1w[ii * 96 + j], e1w[ii * 96 + 48 + j]);
    }
    for (int i = tid; i < 1728; i += 256) m2[i] = e2w[i];
    for (int i = tid; i < 216;  i += 256) m3[i] = e3w[i];
    if (tid < 48) m1b[tid] = e1b[tid];
    if (tid < 36) m2b[tid] = e2b[tid];
    if (tid < 6)  m3b[tid] = e3b[tid];
    __syncthreads();

    int n = blockIdx.x * 256 + tid;

    ull av[48];
    #pragma unroll
    for (int j = 0; j < 48; j++)
        av[j] = pack2(g_hst[0][(size_t)j * NB + n], g_hst[1][(size_t)j * NB + n]);

    float x1l[48];
    #pragma unroll 1
    for (int i = 0; i < 48; i++) {
        ull acc = pack2(m1b[i], 0.f);
        const ull* w = m1p + i * 48;
        #pragma unroll
        for (int j = 0; j < 48; j++) fma2(acc, w[j], av[j]);
        x1l[i] = fmaxf(red2(acc), 0.f);
    }
    #pragma unroll
    for (int j = 0; j < 24; j++) av[j] = pack2(x1l[2*j], x1l[2*j+1]);
    const ull* m2p = (const ull*)m2;
    float x2l[36];
    #pragma unroll 1
    for (int i = 0; i < 36; i++) {
        ull acc = pack2(m2b[i], 0.f);
        const ull* w = m2p + i * 24;
        #pragma unroll
        for (int j = 0; j < 24; j++) fma2(acc, w[j], av[j]);
        x2l[i] = fmaxf(red2(acc), 0.f);
    }
    #pragma unroll
    for (int j = 0; j < 18; j++) av[j] = pack2(x2l[2*j], x2l[2*j+1]);
    const ull* m3p = (const ull*)m3;
    #pragma unroll
    for (int cc = 0; cc < 6; cc++) {
        ull acc = pack2(m3b[cc], 0.f);
        const ull* w = m3p + cc * 18;
        #pragma unroll
        for (int j = 0; j < 18; j++) fma2(acc, w[j], av[j]);
        out[(size_t)n * 6 + cc] = red2(acc);
    }
}

// ===========================================================================
extern "C" void kernel_launch(void* const* d_in, const int* in_sizes, int n_in,
                              void* d_out, int out_size)
{
    const float* nf   = (const float*)d_in[0];
    const float* pos  = (const float*)d_in[1];
    const float* att  = (const float*)d_in[2];
    const float* msgw = (const float*)d_in[3];
    const float* msgb = (const float*)d_in[4];
    const float* gwi  = (const float*)d_in[5];
    const float* gwh  = (const float*)d_in[6];
    const float* gbi  = (const float*)d_in[7];
    const float* gbh  = (const float*)d_in[8];
    const float* wihF = (const float*)d_in[9];
    const float* whhF = (const float*)d_in[10];
    const float* bihF = (const float*)d_in[11];
    const float* bhhF = (const float*)d_in[12];
    const float* wihB = (const float*)d_in[13];
    const float* whhB = (const float*)d_in[14];
    const float* bihB = (const float*)d_in[15];
    const float* bhhB = (const float*)d_in[16];
    const float* e1w  = (const float*)d_in[17];
    const float* e1b  = (const float*)d_in[18];
    const float* e2w  = (const float*)d_in[19];
    const float* e2b  = (const float*)d_in[20];
    const float* e3w  = (const float*)d_in[21];
    const float* e3b  = (const float*)d_in[22];
    float* out = (float*)d_out;

    cudaFuncSetAttribute(lstm_rt_kernel,
                         cudaFuncAttributeMaxDynamicSharedMemorySize, SMEM_L);

    dim3 gA(NB / 128, SS);
    gnn_kernel<<<gA, 128>>>(nf, pos, att, msgw, msgb, gwi, gwh, gbi, gbh);
    lstm_rt_kernel<<<NB / NCB, TPB_L, SMEM_L>>>(
        wihF, whhF, bihF, bhhF, wihB, whhB, bihB, bhhB);
    mlp_kernel<<<NB / 256, 256>>>(e1w, e1b, e2w, e2b, e3w, e3b, out);
}

// round 13
// speedup vs baseline: 1.4478x; 1.1130x over previous
#include <cuda_runtime.h>
#include <cuda_bf16.h>
#include <cstdint>

#define NB 65536
#define SS 5
#define KK 4
#define DD 12
#define HH 48
#define NCB 32        // batch rows per LSTM CTA
#define TPB_L 384     // 48 d  x  8 n-quads
#define SWS 194       // padded ull-stride per d row (1552 B, != 0 mod 128)

typedef unsigned long long ull;

__device__ float g_xbuf[SS * HH * NB];        // [s][feat][n]
__device__ float g_hst[2][(size_t)HH * NB];   // final hidden per dir, [d][n]

// ---------------- helpers ----------------
__device__ __forceinline__ float sigf(float x) {
    return __fdividef(1.0f, 1.0f + __expf(-x));
}
__device__ __forceinline__ float tanhf_(float x) {
    return 1.0f - __fdividef(2.0f, __expf(2.0f * x) + 1.0f);
}
__device__ __forceinline__ ull pack2(float lo, float hi) {
    ull r; asm("mov.b64 %0, {%1, %2};" : "=l"(r) : "f"(lo), "f"(hi)); return r;
}
__device__ __forceinline__ void unpack2(ull v, float& lo, float& hi) {
    asm("mov.b64 {%0, %1}, %2;" : "=f"(lo), "=f"(hi) : "l"(v));
}
__device__ __forceinline__ float red2(ull v) {
    float lo, hi; unpack2(v, lo, hi); return lo + hi;
}
__device__ __forceinline__ void fma2(ull& acc, ull a, ull b) {
    asm("fma.rn.f32x2 %0, %1, %2, %0;" : "+l"(acc) : "l"(a), "l"(b));
}

// n (0..31) -> ull position within a 32-ull act row (conflict-free halves)
__device__ __forceinline__ int act_pos(int n) {
    int q = n >> 2, u = n & 3;
    return (u < 2) ? (q * 2 + u) : (16 + q * 2 + u - 2);
}

// ===========================================================================
// Kernel A: GNN — 4 threads per (n,s), one per node k. Message exchange via
// bank-padded smem; GRU thread-local; coalesced transpose store.
// ===========================================================================
#define GTPB 128
#define NSB  32   // (n,s) pairs per block

__global__ __launch_bounds__(GTPB) void gnn_kernel(
    const float* __restrict__ nf, const float* __restrict__ pos,
    const float* __restrict__ att,
    const float* __restrict__ msgw, const float* __restrict__ msgb,
    const float* __restrict__ gwi, const float* __restrict__ gwh,
    const float* __restrict__ gbi, const float* __restrict__ gbh)
{
    __shared__ float      s_mw[144];
    __shared__ float      s_mb[12];
    __shared__ ulonglong2 sRZ[144];   // (wih_r,whh_r),(wih_z,whh_z)
    __shared__ ull        sN [144];   // (wih_n, whh_n)
    __shared__ ull        sBR[12], sBZ[12], sBN[12];
    __shared__ float      sMA[NSB * 52];   // ma exchange, padded stride
    __shared__ float      sTR[48 * 40];    // transpose-out, padded stride

    int tid = threadIdx.x;
    int ns  = tid >> 2;      // 0..31
    int k   = tid & 3;       // node
    int n   = blockIdx.x * NSB + ns;
    int s   = blockIdx.y;

    for (int i = tid; i < 144; i += GTPB) {
        s_mw[i] = msgw[i];
        int d = i / 12, e = i - d * 12;
        ulonglong2 t;
        t.x = pack2(gwi[d * 12 + e],        gwh[d * 12 + e]);
        t.y = pack2(gwi[(12 + d) * 12 + e], gwh[(12 + d) * 12 + e]);
        sRZ[i] = t;
        sN[i]  = pack2(gwi[(24 + d) * 12 + e], gwh[(24 + d) * 12 + e]);
    }
    if (tid < 12) {
        s_mb[tid] = msgb[tid];
        sBR[tid] = pack2(gbi[tid] + gbh[tid], 0.f);
        sBZ[tid] = pack2(gbi[12 + tid] + gbh[12 + tid], 0.f);
        sBN[tid] = pack2(gbi[24 + tid], gbh[24 + tid]);
    }

    int base = n * SS + s;
    // h = node_feat for own node k: [nodes_feature(6), pos(6)]
    float h[12];
    #pragma unroll
    for (int f = 0; f < 6; f++) h[f]     = nf [base * 24 + k * 6 + f];
    #pragma unroll
    for (int f = 0; f < 6; f++) h[6 + f] = pos[base * 24 + k * 6 + f];
    // attention row a[k][w]
    float4 av4 = *reinterpret_cast<const float4*>(att + (size_t)base * 16 + k * 4);
    float av[4] = {av4.x, av4.y, av4.z, av4.w};

    __syncthreads();   // weights staged

    #pragma unroll 1
    for (int pass = 0; pass < 2; pass++) {
        // message from own node (w = k)
        float ma[12];
        #pragma unroll
        for (int d = 0; d < 12; d++) {
            float acc = s_mb[d];
            #pragma unroll
            for (int e = 0; e < 12; e++) acc += s_mw[d * 12 + e] * h[e];
            ma[d] = acc;
        }
        __syncthreads();   // prior sMA reads done (pass 1) / harmless (pass 0)
        #pragma unroll
        for (int d = 0; d < 12; d++) sMA[ns * 52 + k * 12 + d] = ma[d];
        __syncthreads();

        // mv = attention-weighted sum of all 4 messages
        const float* m = sMA + ns * 52;
        ull gk[12];
        #pragma unroll
        for (int e = 0; e < 12; e++) {
            float mv = av[0] * m[e] + av[1] * m[12 + e] +
                       av[2] * m[24 + e] + av[3] * m[36 + e];
            gk[e] = pack2(mv, h[e]);
        }

        // GRU for own node
        float tmpl[12];
        #pragma unroll 1
        for (int d = 0; d < 12; d++) {
            ull aR = sBR[d], aZ = sBZ[d], aN = sBN[d];
            const ulonglong2* wrz = sRZ + d * 12;
            const ull*        wn  = sN  + d * 12;
            #pragma unroll
            for (int e = 0; e < 12; e++) {
                ulonglong2 w = wrz[e];
                fma2(aR, w.x, gk[e]);
                fma2(aZ, w.y, gk[e]);
                fma2(aN, wn[e], gk[e]);
            }
            float r = sigf(red2(aR));
            float z = sigf(red2(aZ));
            float nlo, nhi; unpack2(aN, nlo, nhi);
            float nn = tanhf_(nlo + r * nhi);
            tmpl[d] = (1.0f - z) * nn + z * h[d];
        }
        #pragma unroll
        for (int d = 0; d < 12; d++) h[d] = tmpl[d];
    }

    // transpose-out: row r = d*4+k, col ns (stride 40 -> conflict-free)
    __syncthreads();
    #pragma unroll
    for (int d = 0; d < 12; d++) sTR[(d * 4 + k) * 40 + ns] = h[d];
    __syncthreads();
    #pragma unroll
    for (int it = 0; it < 12; it++) {
        int r = it * 4 + (tid >> 5);
        int col = tid & 31;
        g_xbuf[(size_t)(s * HH + r) * NB + blockIdx.x * NSB + col] = sTR[r * 40 + col];
    }
}

// ===========================================================================
// Kernel B: register-tiled bidirectional LSTM; mid-step barrier so MUFU
// epilogues overlap the next step's x-FMA. Full unroll.
// ===========================================================================
#define O_W   0                         /* ull[48*SWS] = 74496 B */
#define O_ACT 74496                     /* ull[96*32]  = 24576 B */
#define O_B   (74496 + 24576)           /* float[192] */
#define SMEM_L (O_B + 768 + 16)

__global__ __launch_bounds__(TPB_L, 1) void lstm_rt_kernel(
    const float* __restrict__ wihF, const float* __restrict__ whhF,
    const float* __restrict__ bihF, const float* __restrict__ bhhF,
    const float* __restrict__ wihB, const float* __restrict__ whhB,
    const float* __restrict__ bihB, const float* __restrict__ bhhB)
{
    extern __shared__ char smc[];
    ull*   sW   = (ull*)(smc + O_W);
    ull*   sAct = (ull*)(smc + O_ACT);
    float* sB   = (float*)(smc + O_B);

    int tid = threadIdx.x;
    int d = tid >> 3;
    int q = tid & 7;
    int nb = blockIdx.x * NCB;

    #pragma unroll 1
    for (int dir = 0; dir < 2; dir++) {
        const float* wih = dir ? wihB : wihF;
        const float* whh = dir ? whhB : whhF;
        const float* bih = dir ? bihB : bihF;
        const float* bhh = dir ? bhhB : bhhF;

        __syncthreads();   // previous dir fully done
        for (int i = tid; i < 9216; i += TPB_L) {
            int dd = i / 192;
            int r  = i - dd * 192;
            int kp = r >> 2, g = r & 3;
            int k0 = 2 * kp;
            float w0, w1;
            if (k0 < 48) {
                w0 = wih[(g * 48 + dd) * 48 + k0];
                w1 = wih[(g * 48 + dd) * 48 + k0 + 1];
            } else {
                w0 = whh[(g * 48 + dd) * 48 + (k0 - 48)];
                w1 = whh[(g * 48 + dd) * 48 + (k0 - 47)];
            }
            sW[dd * SWS + r] = pack2(w0, w1);
        }
        for (int i = tid; i < 192; i += TPB_L) {
            int dd = i >> 2, g = i & 3;
            sB[i] = bih[g * 48 + dd] + bhh[g * 48 + dd];
        }
        {
            int s0 = dir ? (SS - 1) : 0;
            #pragma unroll
            for (int rr = 0; rr < 2; rr++) {
                int i = tid + rr * TPB_L;
                int kp = i >> 5, n = i & 31;
                int p = act_pos(n);
                sAct[(48 + kp) * 32 + p] = 0ull;
                sAct[kp * 32 + p] =
                    pack2(g_xbuf[(size_t)(s0 * HH + 2 * kp) * NB + nb + n],
                          g_xbuf[(size_t)(s0 * HH + 2 * kp + 1) * NB + nb + n]);
            }
        }
        __syncthreads();

        float b0 = sB[d * 4 + 0], b1 = sB[d * 4 + 1];
        float b2 = sB[d * 4 + 2], b3 = sB[d * 4 + 3];
        float c[4] = {0.f, 0.f, 0.f, 0.f};

        #pragma unroll 1
        for (int st = 0; st < SS; st++) {
            int xbase = (st & 1) * 24;

            // stage x for step st+1 into the opposite buffer (x rows only;
            // stragglers from st-1 touch h rows only -> disjoint)
            if (st < SS - 1) {
                int nbase = ((st + 1) & 1) * 24;
                int sn = dir ? (SS - 2 - st) : (st + 1);
                #pragma unroll
                for (int rr = 0; rr < 2; rr++) {
                    int i = tid + rr * TPB_L;
                    int kp = i >> 5, n = i & 31;
                    sAct[(nbase + kp) * 32 + act_pos(n)] =
                        pack2(g_xbuf[(size_t)(sn * HH + 2 * kp) * NB + nb + n],
                              g_xbuf[(size_t)(sn * HH + 2 * kp + 1) * NB + nb + n]);
                }
            }

            ull acc[4][4];
            #pragma unroll
            for (int g = 0; g < 4; g++)
                #pragma unroll
                for (int u = 0; u < 4; u++) acc[g][u] = 0ull;

            const ulonglong2* wrow = (const ulonglong2*)(sW + d * SWS);
            const ull* axr = sAct + xbase * 32;
            const ull* ahr = sAct + (48 + xbase) * 32;

            // x-part (x staged one barrier ago -> safe to read pre-barrier)
            #pragma unroll
            for (int kp = 0; kp < 24; kp++) {
                ulonglong2 wA = wrow[kp * 2];
                ulonglong2 wB = wrow[kp * 2 + 1];
                ulonglong2 aA = *(const ulonglong2*)(axr + kp * 32 + q * 2);
                ulonglong2 aB = *(const ulonglong2*)(axr + kp * 32 + 16 + q * 2);
                fma2(acc[0][0], wA.x, aA.x); fma2(acc[1][0], wA.y, aA.x);
                fma2(acc[2][0], wB.x, aA.x); fma2(acc[3][0], wB.y, aA.x);
                fma2(acc[0][1], wA.x, aA.y); fma2(acc[1][1], wA.y, aA.y);
                fma2(acc[2][1], wB.x, aA.y); fma2(acc[3][1], wB.y, aA.y);
                fma2(acc[0][2], wA.x, aB.x); fma2(acc[1][2], wA.y, aB.x);
                fma2(acc[2][2], wB.x, aB.x); fma2(acc[3][2], wB.y, aB.x);
                fma2(acc[0][3], wA.x, aB.y); fma2(acc[1][3], wA.y, aB.y);
                fma2(acc[2][3], wB.x, aB.y); fma2(acc[3][3], wB.y, aB.y);
            }

            __syncthreads();   // h_{st} writes (prev iter tail) + x_{st+1} staging visible

            // h-part
            #pragma unroll
            for (int kp = 0; kp < 24; kp++) {
                ulonglong2 wA = wrow[48 + kp * 2];
                ulonglong2 wB = wrow[48 + kp * 2 + 1];
                ulonglong2 aA = *(const ulonglong2*)(ahr + kp * 32 + q * 2);
                ulonglong2 aB = *(const ulonglong2*)(ahr + kp * 32 + 16 + q * 2);
                fma2(acc[0][0], wA.x, aA.x); fma2(acc[1][0], wA.y, aA.x);
                fma2(acc[2][0], wB.x, aA.x); fma2(acc[3][0], wB.y, aA.x);
                fma2(acc[0][1], wA.x, aA.y); fma2(acc[1][1], wA.y, aA.y);
                fma2(acc[2][1], wB.x, aA.y); fma2(acc[3][1], wB.y, aA.y);
                fma2(acc[0][2], wA.x, aB.x); fma2(acc[1][2], wA.y, aB.x);
                fma2(acc[2][2], wB.x, aB.x); fma2(acc[3][2], wB.y, aB.x);
                fma2(acc[0][3], wA.x, aB.y); fma2(acc[1][3], wA.y, aB.y);
                fma2(acc[2][3], wB.x, aB.y); fma2(acc[3][3], wB.y, aB.y);
            }

            float hv[4];
            #pragma unroll
            for (int u = 0; u < 4; u++) {
                float pI = red2(acc[0][u]) + b0;
                float pF = red2(acc[1][u]) + b1;
                float pG = red2(acc[2][u]) + b2;
                float pO = red2(acc[3][u]) + b3;
                float ig = sigf(pI), fg = sigf(pF);
                float gg = tanhf_(pG), og = sigf(pO);
                float cn = fg * c[u] + ig * gg;
                c[u] = cn;
                hv[u] = og * tanhf_(cn);
            }

            if (st < SS - 1) {
                int nbase = ((st + 1) & 1) * 24;
                float* sAf = (float*)sAct;
                int kp_h = 48 + nbase + (d >> 1), par = d & 1;
                #pragma unroll
                for (int u = 0; u < 4; u++) {
                    int p = act_pos(q * 4 + u);
                    sAf[(kp_h * 32 + p) * 2 + par] = hv[u];
                }
            } else {
                float4 o4 = make_float4(hv[0], hv[1], hv[2], hv[3]);
                *(float4*)&g_hst[dir][(size_t)d * NB + nb + q * 4] = o4;
            }
            // no end-of-step barrier: next step's mid barrier covers it
        } // st
    } // dir
}

// ===========================================================================
// Kernel C: MLP head, one thread per n (f32x2 pairs), smem weights
// ===========================================================================
__global__ __launch_bounds__(256) void mlp_kernel(
    const float* __restrict__ e1w, const float* __restrict__ e1b,
    const float* __restrict__ e2w, const float* __restrict__ e2b,
    const float* __restrict__ e3w, const float* __restrict__ e3b,
    float* __restrict__ out)
{
    __shared__ ull   m1p[2304];
    __shared__ float m1b[48], m2[1728], m2b[36], m3[216], m3b[6];

    int tid = threadIdx.x;
    for (int i = tid; i < 2304; i += 256) {
        int ii = i / 48, j = i - ii * 48;
        m1p[i] = pack2(e1w[ii * 96 + j], e1w[ii * 96 + 48 + j]);
    }
    for (int i = tid; i < 1728; i += 256) m2[i] = e2w[i];
    for (int i = tid; i < 216;  i += 256) m3[i] = e3w[i];
    if (tid < 48) m1b[tid] = e1b[tid];
    if (tid < 36) m2b[tid] = e2b[tid];
    if (tid < 6)  m3b[tid] = e3b[tid];
    __syncthreads();

    int n = blockIdx.x * 256 + tid;

    ull av[48];
    #pragma unroll
    for (int j = 0; j < 48; j++)
        av[j] = pack2(g_hst[0][(size_t)j * NB + n], g_hst[1][(size_t)j * NB + n]);

    float x1l[48];
    #pragma unroll 1
    for (int i = 0; i < 48; i++) {
        ull acc = pack2(m1b[i], 0.f);
        const ull* w = m1p + i * 48;
        #pragma unroll
        for (int j = 0; j < 48; j++) fma2(acc, w[j], av[j]);
        x1l[i] = fmaxf(red2(acc), 0.f);
    }
    #pragma unroll
    for (int j = 0; j < 24; j++) av[j] = pack2(x1l[2*j], x1l[2*j+1]);
    const ull* m2p = (const ull*)m2;
    float x2l[36];
    #pragma unroll 1
    for (int i = 0; i < 36; i++) {
        ull acc = pack2(m2b[i], 0.f);
        const ull* w = m2p + i * 24;
        #pragma unroll
        for (int j = 0; j < 24; j++) fma2(acc, w[j], av[j]);
        x2l[i] = fmaxf(red2(acc), 0.f);
    }
    #pragma unroll
    for (int j = 0; j < 18; j++) av[j] = pack2(x2l[2*j], x2l[2*j+1]);
    const ull* m3p = (const ull*)m3;
    #pragma unroll
    for (int cc = 0; cc < 6; cc++) {
        ull acc = pack2(m3b[cc], 0.f);
        const ull* w = m3p + cc * 18;
        #pragma unroll
        for (int j = 0; j < 18; j++) fma2(acc, w[j], av[j]);
        out[(size_t)n * 6 + cc] = red2(acc);
    }
}

// ===========================================================================
extern "C" void kernel_launch(void* const* d_in, const int* in_sizes, int n_in,
                              void* d_out, int out_size)
{
    const float* nf   = (const float*)d_in[0];
    const float* pos  = (const float*)d_in[1];
    const float* att  = (const float*)d_in[2];
    const float* msgw = (const float*)d_in[3];
    const float* msgb = (const float*)d_in[4];
    const float* gwi  = (const float*)d_in[5];
    const float* gwh  = (const float*)d_in[6];
    const float* gbi  = (const float*)d_in[7];
    const float* gbh  = (const float*)d_in[8];
    const float* wihF = (const float*)d_in[9];
    const float* whhF = (const float*)d_in[10];
    const float* bihF = (const float*)d_in[11];
    const float* bhhF = (const float*)d_in[12];
    const float* wihB = (const float*)d_in[13];
    const float* whhB = (const float*)d_in[14];
    const float* bihB = (const float*)d_in[15];
    const float* bhhB = (const float*)d_in[16];
    const float* e1w  = (const float*)d_in[17];
    const float* e1b  = (const float*)d_in[18];
    const float* e2w  = (const float*)d_in[19];
    const float* e2b  = (const float*)d_in[20];
    const float* e3w  = (const float*)d_in[21];
    const float* e3b  = (const float*)d_in[22];
    float* out = (float*)d_out;

    cudaFuncSetAttribute(lstm_rt_kernel,
                         cudaFuncAttributeMaxDynamicSharedMemorySize, SMEM_L);

    dim3 gA(NB / NSB, SS);
    gnn_kernel<<<gA, GTPB>>>(nf, pos, att, msgw, msgb, gwi, gwh, gbi, gbh);
    lstm_rt_kernel<<<NB / NCB, TPB_L, SMEM_L>>>(
        wihF, whhF, bihF, bhhF, wihB, whhB, bihB, bhhB);
    mlp_kernel<<<NB / 256, 256>>>(e1w, e1b, e2w, e2b, e3w, e3b, out);
}